// round 4
// baseline (speedup 1.0000x reference)
#include <cuda_runtime.h>
#include <cuda_bf16.h>
#include <math.h>
#include <stdint.h>

// ---------------- problem constants ----------------
#define T_TOK 16384
#define DIM   1024
#define HID   2048
#define NEXP  8
#define TOPK  2
#define NSLOT (T_TOK*TOPK)                 // 32768
#define PADT  (NSLOT + NEXP*128)           // 33792 padded rows

typedef __nv_bfloat16 bf16;

// ---------------- device scratch (allocation-free rule) ----------------
__device__ int   g_counts[NEXP];
__device__ int   g_cntpad[NEXP];
__device__ int   g_offsets[NEXP];
__device__ int   g_cursors[NEXP];
__device__ int   g_perm[PADT];
__device__ int   g_rowOf[NSLOT];
__device__ int   g_sel[NSLOT];
__device__ float g_gwt[NSLOT];

__device__ bf16  g_w1h[(size_t)NEXP*HID*DIM];
__device__ bf16  g_w1l[(size_t)NEXP*HID*DIM];
__device__ bf16  g_w3h[(size_t)NEXP*HID*DIM];
__device__ bf16  g_w3l[(size_t)NEXP*HID*DIM];
__device__ bf16  g_w2h[(size_t)NEXP*DIM*HID];
__device__ bf16  g_w2l[(size_t)NEXP*DIM*HID];
__device__ bf16  g_xh[(size_t)PADT*DIM];
__device__ bf16  g_xl[(size_t)PADT*DIM];
__device__ bf16  g_hh[(size_t)PADT*HID];
__device__ bf16  g_hl[(size_t)PADT*HID];
__device__ float g_y [(size_t)PADT*DIM];

// ---------------- helpers (base-PTX only) ----------------
__device__ __forceinline__ uint32_t smem_u32(const void* p) {
    uint32_t a;
    asm("{ .reg .u64 t; cvta.to.shared.u64 t, %1; cvt.u32.u64 %0, t; }" : "=r"(a) : "l"(p));
    return a;
}
__device__ __forceinline__ void cp16(uint32_t dst, const void* src) {
    asm volatile("cp.async.cg.shared.global [%0], [%1], 16;" :: "r"(dst), "l"(src));
}
__device__ __forceinline__ void cp_commit() {
    asm volatile("cp.async.commit_group;");
}
__device__ __forceinline__ void cp_wait0() {
    asm volatile("cp.async.wait_group 0;" ::: "memory");
}
__device__ __forceinline__ void cp_wait1() {
    asm volatile("cp.async.wait_group 1;" ::: "memory");
}
// m16n8k16 row.col bf16 -> f32 accum (base PTX, HMMA pipe)
__device__ __forceinline__ void mma_bf16(float c[4], uint32_t a0, uint32_t a1,
                                         uint32_t a2, uint32_t a3,
                                         uint32_t b0, uint32_t b1) {
    asm volatile(
        "mma.sync.aligned.m16n8k16.row.col.f32.bf16.bf16.f32 "
        "{%0,%1,%2,%3}, {%4,%5,%6,%7}, {%8,%9}, {%0,%1,%2,%3};"
        : "+f"(c[0]), "+f"(c[1]), "+f"(c[2]), "+f"(c[3])
        : "r"(a0), "r"(a1), "r"(a2), "r"(a3), "r"(b0), "r"(b1));
}

// ---------------- kernel: weight convert (+ zero counters) ----------------
#define WQ ((size_t)NEXP*HID*DIM/4)
__global__ __launch_bounds__(256) void wconv_kernel(const float* __restrict__ w1,
                                                    const float* __restrict__ w3,
                                                    const float* __restrict__ w2) {
    if (blockIdx.x == 0 && threadIdx.x < NEXP) g_counts[threadIdx.x] = 0;
    size_t i = (size_t)blockIdx.x * blockDim.x + threadIdx.x;
    if (i >= 3 * WQ) return;
    const float* src; bf16 *hi, *lo; size_t j;
    if (i < WQ)           { src = w1; hi = g_w1h; lo = g_w1l; j = i; }
    else if (i < 2 * WQ)  { src = w3; hi = g_w3h; lo = g_w3l; j = i - WQ; }
    else                  { src = w2; hi = g_w2h; lo = g_w2l; j = i - 2 * WQ; }
    float4 v = ((const float4*)src)[j];
    __nv_bfloat162 h0, h1, l0, l1;
    h0.x = __float2bfloat16(v.x); h0.y = __float2bfloat16(v.y);
    h1.x = __float2bfloat16(v.z); h1.y = __float2bfloat16(v.w);
    l0.x = __float2bfloat16(v.x - __bfloat162float(h0.x));
    l0.y = __float2bfloat16(v.y - __bfloat162float(h0.y));
    l1.x = __float2bfloat16(v.z - __bfloat162float(h1.x));
    l1.y = __float2bfloat16(v.w - __bfloat162float(h1.y));
    ((__nv_bfloat162*)(hi + 4 * j))[0] = h0;
    ((__nv_bfloat162*)(hi + 4 * j))[1] = h1;
    ((__nv_bfloat162*)(lo + 4 * j))[0] = l0;
    ((__nv_bfloat162*)(lo + 4 * j))[1] = l1;
}

// ---------------- gating (1 warp / token) ----------------
__global__ void gating_kernel(const float* __restrict__ x, const float* __restrict__ gw) {
    int t = (blockIdx.x * blockDim.x + threadIdx.x) >> 5;
    int lane = threadIdx.x & 31;
    if (t >= T_TOK) return;
    const float* xr = x + (size_t)t * DIM;
    float xv[DIM / 32];
#pragma unroll
    for (int i = 0; i < DIM / 32; i++) xv[i] = xr[lane + 32 * i];
    float logits[NEXP];
#pragma unroll
    for (int e = 0; e < NEXP; e++) {
        const float* g = gw + e * DIM;
        float acc = 0.f;
#pragma unroll
        for (int i = 0; i < DIM / 32; i++) acc = fmaf(xv[i], g[lane + 32 * i], acc);
#pragma unroll
        for (int o = 16; o; o >>= 1) acc += __shfl_xor_sync(0xffffffffu, acc, o);
        logits[e] = acc;
    }
    if (lane == 0) {
        int e0 = 0; float l0 = logits[0];
#pragma unroll
        for (int e = 1; e < NEXP; e++) if (logits[e] > l0) { l0 = logits[e]; e0 = e; }
        int e1 = (e0 == 0) ? 1 : 0; float l1 = logits[e1];
#pragma unroll
        for (int e = 0; e < NEXP; e++) if (e != e0 && logits[e] > l1) { l1 = logits[e]; e1 = e; }
        float p1 = __expf(l1 - l0);
        float inv = 1.f / (1.f + p1);
        g_sel[t * 2 + 0] = e0; g_sel[t * 2 + 1] = e1;
        g_gwt[t * 2 + 0] = inv; g_gwt[t * 2 + 1] = p1 * inv;
        atomicAdd(&g_counts[e0], 1);
        atomicAdd(&g_counts[e1], 1);
    }
}

// ---------------- scan ----------------
__global__ void scan_kernel() {
    int o = 0;
    for (int e = 0; e < NEXP; e++) {
        int c = g_counts[e];
        int cp = (c + 127) & ~127;
        g_offsets[e] = o; g_cursors[e] = o; g_cntpad[e] = cp;
        o += cp;
    }
}

// ---------------- scatter ----------------
__global__ void scatter_kernel() {
    int idx = blockIdx.x * blockDim.x + threadIdx.x;
    if (idx >= NSLOT) return;
    int e = g_sel[idx];
    int pos = atomicAdd(&g_cursors[e], 1);
    g_perm[pos] = idx >> 1;
    g_rowOf[idx] = pos;
}

// ---------------- gather + convert x -> padded bf16 hi/lo ----------------
__global__ __launch_bounds__(256) void gather_kernel(const float* __restrict__ x) {
    int row = blockIdx.x;
    int e = -1, r = 0;
#pragma unroll
    for (int i = 0; i < NEXP; i++) {
        int o = g_offsets[i], c = g_cntpad[i];
        if (row >= o && row < o + c) { e = i; r = row - o; }
    }
    if (e < 0) return;
    float4 v = make_float4(0.f, 0.f, 0.f, 0.f);
    if (r < g_counts[e]) {
        int tok = g_perm[row];
        v = *(const float4*)(x + (size_t)tok * DIM + threadIdx.x * 4);
    }
    size_t o = (size_t)row * DIM + threadIdx.x * 4;
    __nv_bfloat162 h0, h1, l0, l1;
    h0.x = __float2bfloat16(v.x); h0.y = __float2bfloat16(v.y);
    h1.x = __float2bfloat16(v.z); h1.y = __float2bfloat16(v.w);
    l0.x = __float2bfloat16(v.x - __bfloat162float(h0.x));
    l0.y = __float2bfloat16(v.y - __bfloat162float(h0.y));
    l1.x = __float2bfloat16(v.z - __bfloat162float(h1.x));
    l1.y = __float2bfloat16(v.w - __bfloat162float(h1.y));
    ((__nv_bfloat162*)(g_xh + o))[0] = h0; ((__nv_bfloat162*)(g_xh + o))[1] = h1;
    ((__nv_bfloat162*)(g_xl + o))[0] = l0; ((__nv_bfloat162*)(g_xl + o))[1] = l1;
}

// ---------------- shared memory layouts ----------------
// Row stride 40 halves = 80 bytes: 16B-aligned, conflict-free across 8 rows.
#define SAW 80
// GEMM1 stage: A hi/lo [128x32], B1 hi/lo [64x32], B3 hi/lo [64x32]
#define G1_AH  0
#define G1_AL  10240
#define G1_B1H 20480
#define G1_B1L 25600
#define G1_B3H 30720
#define G1_B3L 35840
#define G1_STAGE 40960
#define G1_SMEM (2*G1_STAGE)
// GEMM2 stage: A hi/lo [128x32], B hi/lo [128x32]
#define G2_AH  0
#define G2_AL  10240
#define G2_BH  20480
#define G2_BL  30720
#define G2_STAGE 40960
#define G2_SMEM (2*G2_STAGE)

// ---------------- GEMM1: hidden = silu(x@w1^T) * (x@w3^T) -------------------
// CTA tile 128(M) x 64(N), both outputs; K-chunk 32; bf16x3.
__device__ __forceinline__ void g1_load(uint32_t st,
        const bf16* Ah, const bf16* Al,
        const bf16* B1h, const bf16* B1l,
        const bf16* B3h, const bf16* B3l, int kt, int tid) {
#pragma unroll
    for (int i = 0; i < 2; i++) {
        int idx = tid + i * 256;
        int m = idx >> 2, c = idx & 3;
        cp16(st + G1_AH + m * SAW + c * 16, Ah + (size_t)m * DIM + kt + c * 8);
        cp16(st + G1_AL + m * SAW + c * 16, Al + (size_t)m * DIM + kt + c * 8);
    }
    {
        int n = tid >> 2, c = tid & 3;
        cp16(st + G1_B1H + n * SAW + c * 16, B1h + (size_t)n * DIM + kt + c * 8);
        cp16(st + G1_B1L + n * SAW + c * 16, B1l + (size_t)n * DIM + kt + c * 8);
        cp16(st + G1_B3H + n * SAW + c * 16, B3h + (size_t)n * DIM + kt + c * 8);
        cp16(st + G1_B3L + n * SAW + c * 16, B3l + (size_t)n * DIM + kt + c * 8);
    }
}

__global__ __launch_bounds__(256, 1) void gemm1_mma() {
    int e = blockIdx.z;
    int m0blk = blockIdx.y * 128;
    if (m0blk >= g_cntpad[e]) return;
    int row0 = g_offsets[e] + m0blk;
    int n0 = blockIdx.x * 64;

    extern __shared__ __align__(16) char smem[];
    uint32_t sb = smem_u32(smem);
    int tid = threadIdx.x, lane = tid & 31, warp = tid >> 5;
    int gr = lane >> 2, gc2 = (lane & 3) * 2;
    int wm = (warp & 3) * 32;          // 4 warps along M
    int wn = (warp >> 2) * 32;         // 2 warps along N

    const bf16* Ah  = g_xh  + (size_t)row0 * DIM;
    const bf16* Al  = g_xl  + (size_t)row0 * DIM;
    const size_t wb = ((size_t)e * HID + n0) * DIM;
    const bf16* B1h = g_w1h + wb;
    const bf16* B1l = g_w1l + wb;
    const bf16* B3h = g_w3h + wb;
    const bf16* B3l = g_w3l + wb;

    float acc1[2][4][4], acc3[2][4][4];
#pragma unroll
    for (int i = 0; i < 2; i++)
#pragma unroll
        for (int j = 0; j < 4; j++)
#pragma unroll
            for (int q = 0; q < 4; q++) { acc1[i][j][q] = 0.f; acc3[i][j][q] = 0.f; }

    const int NK = DIM / 32;   // 32
    g1_load(sb, Ah, Al, B1h, B1l, B3h, B3l, 0, tid);
    cp_commit();

#pragma unroll 1
    for (int kc = 0; kc < NK; kc++) {
        if (kc + 1 < NK) {
            g1_load(sb + ((kc + 1) & 1) * G1_STAGE, Ah, Al, B1h, B1l, B3h, B3l,
                    (kc + 1) * 32, tid);
            cp_commit();
            cp_wait1();
        } else {
            cp_wait0();
        }
        __syncthreads();
        const char* st = smem + (kc & 1) * G1_STAGE;
#pragma unroll
        for (int p = 0; p < 3; p++) {
            const char* aB  = st + (p == 2 ? G1_AL  : G1_AH);
            const char* b1B = st + (p == 1 ? G1_B1L : G1_B1H);
            const char* b3B = st + (p == 1 ? G1_B3L : G1_B3H);
#pragma unroll
            for (int ks = 0; ks < 2; ks++) {
                int k0 = ks * 16;
                uint32_t a[2][4];
#pragma unroll
                for (int i = 0; i < 2; i++) {
                    const char* ab = aB + (wm + i * 16 + gr) * SAW + (k0 + gc2) * 2;
                    a[i][0] = *(const uint32_t*)ab;
                    a[i][1] = *(const uint32_t*)(ab + 8 * SAW);
                    a[i][2] = *(const uint32_t*)(ab + 16);
                    a[i][3] = *(const uint32_t*)(ab + 8 * SAW + 16);
                }
#pragma unroll
                for (int j = 0; j < 4; j++) {
                    const char* bb1 = b1B + (wn + j * 8 + gr) * SAW + (k0 + gc2) * 2;
                    const char* bb3 = b3B + (wn + j * 8 + gr) * SAW + (k0 + gc2) * 2;
                    uint32_t b10 = *(const uint32_t*)bb1, b11 = *(const uint32_t*)(bb1 + 16);
                    uint32_t b30 = *(const uint32_t*)bb3, b31 = *(const uint32_t*)(bb3 + 16);
#pragma unroll
                    for (int i = 0; i < 2; i++) {
                        mma_bf16(acc1[i][j], a[i][0], a[i][1], a[i][2], a[i][3], b10, b11);
                        mma_bf16(acc3[i][j], a[i][0], a[i][1], a[i][2], a[i][3], b30, b31);
                    }
                }
            }
        }
        __syncthreads();
    }

    // epilogue: silu(h1)*h3 -> bf16 hi/lo
#pragma unroll
    for (int i = 0; i < 2; i++)
#pragma unroll
        for (int j = 0; j < 4; j++) {
            int m = wm + i * 16 + gr;
            int n = wn + j * 8 + gc2;
#pragma unroll
            for (int half = 0; half < 2; half++) {
                int mm = m + half * 8;
                float h1a = acc1[i][j][half * 2 + 0], h1b = acc1[i][j][half * 2 + 1];
                float h3a = acc3[i][j][half * 2 + 0], h3b = acc3[i][j][half * 2 + 1];
                float v0 = h3a * h1a / (1.f + __expf(-h1a));
                float v1 = h3b * h1b / (1.f + __expf(-h1b));
                size_t idx = (size_t)(row0 + mm) * HID + n0 + n;
                __nv_bfloat162 hh, ll;
                hh.x = __float2bfloat16(v0); hh.y = __float2bfloat16(v1);
                ll.x = __float2bfloat16(v0 - __bfloat162float(hh.x));
                ll.y = __float2bfloat16(v1 - __bfloat162float(hh.y));
                *(__nv_bfloat162*)(g_hh + idx) = hh;
                *(__nv_bfloat162*)(g_hl + idx) = ll;
            }
        }
}

// ---------------- GEMM2: y = hidden @ w2^T ----------------------------------
// CTA tile 128(M) x 128(N); K-chunk 32; bf16x3.
__device__ __forceinline__ void g2_load(uint32_t st,
        const bf16* Ah, const bf16* Al,
        const bf16* Bh, const bf16* Bl, int kt, int tid) {
#pragma unroll
    for (int i = 0; i < 2; i++) {
        int idx = tid + i * 256;
        int m = idx >> 2, c = idx & 3;
        cp16(st + G2_AH + m * SAW + c * 16, Ah + (size_t)m * HID + kt + c * 8);
        cp16(st + G2_AL + m * SAW + c * 16, Al + (size_t)m * HID + kt + c * 8);
        cp16(st + G2_BH + m * SAW + c * 16, Bh + (size_t)m * HID + kt + c * 8);
        cp16(st + G2_BL + m * SAW + c * 16, Bl + (size_t)m * HID + kt + c * 8);
    }
}

__global__ __launch_bounds__(256, 1) void gemm2_mma() {
    int e = blockIdx.z;
    int m0blk = blockIdx.y * 128;
    if (m0blk >= g_cntpad[e]) return;
    int row0 = g_offsets[e] + m0blk;
    int n0 = blockIdx.x * 128;

    extern __shared__ __align__(16) char smem[];
    uint32_t sb = smem_u32(smem);
    int tid = threadIdx.x, lane = tid & 31, warp = tid >> 5;
    int gr = lane >> 2, gc2 = (lane & 3) * 2;
    int wm = (warp & 3) * 32;          // 4 warps along M
    int wn = (warp >> 2) * 64;         // 2 warps along N (64 each)

    const bf16* Ah = g_hh + (size_t)row0 * HID;
    const bf16* Al = g_hl + (size_t)row0 * HID;
    const size_t wb = ((size_t)e * DIM + n0) * HID;
    const bf16* Bh = g_w2h + wb;
    const bf16* Bl = g_w2l + wb;

    float acc[2][8][4];
#pragma unroll
    for (int i = 0; i < 2; i++)
#pragma unroll
        for (int j = 0; j < 8; j++)
#pragma unroll
            for (int q = 0; q < 4; q++) acc[i][j][q] = 0.f;

    const int NK = HID / 32;   // 64
    g2_load(sb, Ah, Al, Bh, Bl, 0, tid);
    cp_commit();

#pragma unroll 1
    for (int kc = 0; kc < NK; kc++) {
        if (kc + 1 < NK) {
            g2_load(sb + ((kc + 1) & 1) * G2_STAGE, Ah, Al, Bh, Bl, (kc + 1) * 32, tid);
            cp_commit();
            cp_wait1();
        } else {
            cp_wait0();
        }
        __syncthreads();
        const char* st = smem + (kc & 1) * G2_STAGE;
#pragma unroll
        for (int p = 0; p < 3; p++) {
            const char* aB = st + (p == 2 ? G2_AL : G2_AH);
            const char* bB = st + (p == 1 ? G2_BL : G2_BH);
#pragma unroll
            for (int ks = 0; ks < 2; ks++) {
                int k0 = ks * 16;
                uint32_t a[2][4];
#pragma unroll
                for (int i = 0; i < 2; i++) {
                    const char* ab = aB + (wm + i * 16 + gr) * SAW + (k0 + gc2) * 2;
                    a[i][0] = *(const uint32_t*)ab;
                    a[i][1] = *(const uint32_t*)(ab + 8 * SAW);
                    a[i][2] = *(const uint32_t*)(ab + 16);
                    a[i][3] = *(const uint32_t*)(ab + 8 * SAW + 16);
                }
#pragma unroll
                for (int j = 0; j < 8; j++) {
                    const char* bb = bB + (wn + j * 8 + gr) * SAW + (k0 + gc2) * 2;
                    uint32_t b0 = *(const uint32_t*)bb, b1 = *(const uint32_t*)(bb + 16);
#pragma unroll
                    for (int i = 0; i < 2; i++)
                        mma_bf16(acc[i][j], a[i][0], a[i][1], a[i][2], a[i][3], b0, b1);
                }
            }
        }
        __syncthreads();
    }

#pragma unroll
    for (int i = 0; i < 2; i++)
#pragma unroll
        for (int j = 0; j < 8; j++) {
            int m = wm + i * 16 + gr;
            int n = wn + j * 8 + gc2;
#pragma unroll
            for (int half = 0; half < 2; half++) {
                int mm = m + half * 8;
                float2 v = make_float2(acc[i][j][half * 2 + 0], acc[i][j][half * 2 + 1]);
                *(float2*)(g_y + (size_t)(row0 + mm) * DIM + n0 + n) = v;
            }
        }
}

// ---------------- combine ----------------
__global__ void combine_kernel(float* __restrict__ out) {
    int idx = blockIdx.x * blockDim.x + threadIdx.x;
    if (idx >= T_TOK * DIM / 4) return;
    int t = idx / (DIM / 4);
    int d4 = idx - t * (DIM / 4);
    float w0 = g_gwt[t * 2 + 0], w1 = g_gwt[t * 2 + 1];
    const float4 y0 = *(const float4*)(g_y + (size_t)g_rowOf[t * 2 + 0] * DIM + d4 * 4);
    const float4 y1 = *(const float4*)(g_y + (size_t)g_rowOf[t * 2 + 1] * DIM + d4 * 4);
    float4 o;
    o.x = w0 * y0.x + w1 * y1.x;
    o.y = w0 * y0.y + w1 * y1.y;
    o.z = w0 * y0.z + w1 * y1.z;
    o.w = w0 * y0.w + w1 * y1.w;
    ((float4*)out)[idx] = o;
}

// ---------------- launch ----------------
extern "C" void kernel_launch(void* const* d_in, const int* in_sizes, int n_in,
                              void* d_out, int out_size) {
    const float* x  = (const float*)d_in[0];
    const float* gw = (const float*)d_in[1];
    const float* w1 = (const float*)d_in[2];
    const float* w3 = (const float*)d_in[3];
    const float* w2 = (const float*)d_in[4];
    float* out = (float*)d_out;

    static int attr_done = 0;
    if (!attr_done) {
        cudaFuncSetAttribute(gemm1_mma, cudaFuncAttributeMaxDynamicSharedMemorySize, G1_SMEM);
        cudaFuncSetAttribute(gemm2_mma, cudaFuncAttributeMaxDynamicSharedMemorySize, G2_SMEM);
        attr_done = 1;
    }

    size_t nq = 3 * WQ;
    wconv_kernel<<<(unsigned)((nq + 255) / 256), 256>>>(w1, w3, w2);   // 0
    gating_kernel<<<T_TOK / 8, 256>>>(x, gw);                          // 1
    scan_kernel<<<1, 1>>>();                                           // 2
    scatter_kernel<<<(NSLOT + 255) / 256, 256>>>();                    // 3
    gather_kernel<<<PADT, 256>>>(x);                                   // 4
    gemm1_mma<<<dim3(HID / 64, 128, NEXP), 256, G1_SMEM>>>();          // 5  (ncu -s 5)
    gemm2_mma<<<dim3(DIM / 128, 128, NEXP), 256, G2_SMEM>>>();         // 6
    combine_kernel<<<(T_TOK * DIM / 4 + 255) / 256, 256>>>(out);       // 7
}

// round 5
// speedup vs baseline: 1.0100x; 1.0100x over previous
#include <cuda_runtime.h>
#include <cuda_bf16.h>
#include <math.h>
#include <stdint.h>

// ---------------- problem constants ----------------
#define T_TOK 16384
#define DIM   1024
#define HID   2048
#define NEXP  8
#define TOPK  2
#define NSLOT (T_TOK*TOPK)                 // 32768
#define PADT  (NSLOT + NEXP*128)           // 33792 padded rows

typedef __nv_bfloat16 bf16;

// ---------------- device scratch (allocation-free rule) ----------------
__device__ int   g_counts[NEXP];
__device__ int   g_cntpad[NEXP];
__device__ int   g_offsets[NEXP];
__device__ int   g_perm[PADT];
__device__ int   g_rowOf[NSLOT];
__device__ int   g_sel[NSLOT];
__device__ float g_gwt[NSLOT];

__device__ bf16  g_w1h[(size_t)NEXP*HID*DIM];
__device__ bf16  g_w1l[(size_t)NEXP*HID*DIM];
__device__ bf16  g_w3h[(size_t)NEXP*HID*DIM];
__device__ bf16  g_w3l[(size_t)NEXP*HID*DIM];
__device__ bf16  g_w2h[(size_t)NEXP*DIM*HID];
__device__ bf16  g_w2l[(size_t)NEXP*DIM*HID];
__device__ bf16  g_xh[(size_t)PADT*DIM];
__device__ bf16  g_xl[(size_t)PADT*DIM];
__device__ bf16  g_hh[(size_t)PADT*HID];
__device__ bf16  g_hl[(size_t)PADT*HID];
__device__ float g_y [(size_t)PADT*DIM];

// ---------------- helpers (base-PTX only) ----------------
__device__ __forceinline__ uint32_t smem_u32(const void* p) {
    uint32_t a;
    asm("{ .reg .u64 t; cvta.to.shared.u64 t, %1; cvt.u32.u64 %0, t; }" : "=r"(a) : "l"(p));
    return a;
}
__device__ __forceinline__ void cp16(uint32_t dst, const void* src) {
    asm volatile("cp.async.cg.shared.global [%0], [%1], 16;" :: "r"(dst), "l"(src));
}
__device__ __forceinline__ void cp_commit() {
    asm volatile("cp.async.commit_group;");
}
__device__ __forceinline__ void cp_wait0() {
    asm volatile("cp.async.wait_group 0;" ::: "memory");
}
__device__ __forceinline__ void mma_bf16(float c[4], uint32_t a0, uint32_t a1,
                                         uint32_t a2, uint32_t a3,
                                         uint32_t b0, uint32_t b1) {
    asm volatile(
        "mma.sync.aligned.m16n8k16.row.col.f32.bf16.bf16.f32 "
        "{%0,%1,%2,%3}, {%4,%5,%6,%7}, {%8,%9}, {%0,%1,%2,%3};"
        : "+f"(c[0]), "+f"(c[1]), "+f"(c[2]), "+f"(c[3])
        : "r"(a0), "r"(a1), "r"(a2), "r"(a3), "r"(b0), "r"(b1));
}
__device__ __forceinline__ void ldm_x4(uint32_t& r0, uint32_t& r1,
                                       uint32_t& r2, uint32_t& r3, uint32_t a) {
    asm volatile("ldmatrix.sync.aligned.m8n8.x4.shared.b16 {%0,%1,%2,%3}, [%4];"
                 : "=r"(r0), "=r"(r1), "=r"(r2), "=r"(r3) : "r"(a));
}

// ---------------- launch 0: gating (1 warp / token, no global atomics) ------
__global__ void gating_kernel(const float* __restrict__ x, const float* __restrict__ gw) {
    int t = (blockIdx.x * blockDim.x + threadIdx.x) >> 5;
    int lane = threadIdx.x & 31;
    if (t >= T_TOK) return;
    const float* xr = x + (size_t)t * DIM;
    float xv[DIM / 32];
#pragma unroll
    for (int i = 0; i < DIM / 32; i++) xv[i] = xr[lane + 32 * i];
    float logits[NEXP];
#pragma unroll
    for (int e = 0; e < NEXP; e++) {
        const float* g = gw + e * DIM;
        float acc = 0.f;
#pragma unroll
        for (int i = 0; i < DIM / 32; i++) acc = fmaf(xv[i], g[lane + 32 * i], acc);
#pragma unroll
        for (int o = 16; o; o >>= 1) acc += __shfl_xor_sync(0xffffffffu, acc, o);
        logits[e] = acc;
    }
    if (lane == 0) {
        int e0 = 0; float l0 = logits[0];
#pragma unroll
        for (int e = 1; e < NEXP; e++) if (logits[e] > l0) { l0 = logits[e]; e0 = e; }
        int e1 = (e0 == 0) ? 1 : 0; float l1 = logits[e1];
#pragma unroll
        for (int e = 0; e < NEXP; e++) if (e != e0 && logits[e] > l1) { l1 = logits[e]; e1 = e; }
        float p1 = __expf(l1 - l0);
        float inv = 1.f / (1.f + p1);
        g_sel[t * 2 + 0] = e0; g_sel[t * 2 + 1] = e1;
        g_gwt[t * 2 + 0] = inv; g_gwt[t * 2 + 1] = p1 * inv;
    }
}

// ---------------- launch 1: count + scan + scatter (single block) -----------
__global__ __launch_bounds__(1024) void scatscan_kernel() {
    __shared__ int scnt[NEXP];
    __shared__ int scur[NEXP];
    int tid = threadIdx.x;
    if (tid < NEXP) scnt[tid] = 0;
    __syncthreads();
    for (int idx = tid; idx < NSLOT; idx += 1024)
        atomicAdd(&scnt[g_sel[idx]], 1);
    __syncthreads();
    if (tid == 0) {
        int o = 0;
        for (int e = 0; e < NEXP; e++) {
            int c = scnt[e];
            int cp = (c + 127) & ~127;
            g_counts[e] = c;
            g_offsets[e] = o;
            g_cntpad[e] = cp;
            scur[e] = o;
            o += cp;
        }
    }
    __syncthreads();
    for (int idx = tid; idx < NSLOT; idx += 1024) {
        int e = g_sel[idx];
        int pos = atomicAdd(&scur[e], 1);
        g_perm[pos] = idx >> 1;
        g_rowOf[idx] = pos;
    }
}

// ---------------- launch 2: prep = gather(x) + weight convert ---------------
#define WQ ((size_t)NEXP*HID*DIM/4)        // float4 per weight tensor
#define WBLK ((unsigned)((3*WQ + 255) / 256))
__global__ __launch_bounds__(256) void prep_kernel(const float* __restrict__ x,
                                                   const float* __restrict__ w1,
                                                   const float* __restrict__ w3,
                                                   const float* __restrict__ w2) {
    int b = blockIdx.x;
    if (b < PADT) {
        // gather + fp32 -> bf16 hi/lo of activations
        int row = b;
        int e = -1, r = 0;
#pragma unroll
        for (int i = 0; i < NEXP; i++) {
            int o = g_offsets[i], c = g_cntpad[i];
            if (row >= o && row < o + c) { e = i; r = row - o; }
        }
        if (e < 0) return;
        float4 v = make_float4(0.f, 0.f, 0.f, 0.f);
        if (r < g_counts[e]) {
            int tok = g_perm[row];
            v = *(const float4*)(x + (size_t)tok * DIM + threadIdx.x * 4);
        }
        size_t o = (size_t)row * DIM + threadIdx.x * 4;
        __nv_bfloat162 h0, h1, l0, l1;
        h0.x = __float2bfloat16(v.x); h0.y = __float2bfloat16(v.y);
        h1.x = __float2bfloat16(v.z); h1.y = __float2bfloat16(v.w);
        l0.x = __float2bfloat16(v.x - __bfloat162float(h0.x));
        l0.y = __float2bfloat16(v.y - __bfloat162float(h0.y));
        l1.x = __float2bfloat16(v.z - __bfloat162float(h1.x));
        l1.y = __float2bfloat16(v.w - __bfloat162float(h1.y));
        ((__nv_bfloat162*)(g_xh + o))[0] = h0; ((__nv_bfloat162*)(g_xh + o))[1] = h1;
        ((__nv_bfloat162*)(g_xl + o))[0] = l0; ((__nv_bfloat162*)(g_xl + o))[1] = l1;
    } else {
        // weight convert
        size_t i = (size_t)(b - PADT) * 256 + threadIdx.x;
        if (i >= 3 * WQ) return;
        const float* src; bf16 *hi, *lo; size_t j;
        if (i < WQ)          { src = w1; hi = g_w1h; lo = g_w1l; j = i; }
        else if (i < 2 * WQ) { src = w3; hi = g_w3h; lo = g_w3l; j = i - WQ; }
        else                 { src = w2; hi = g_w2h; lo = g_w2l; j = i - 2 * WQ; }
        float4 v = ((const float4*)src)[j];
        __nv_bfloat162 h0, h1, l0, l1;
        h0.x = __float2bfloat16(v.x); h0.y = __float2bfloat16(v.y);
        h1.x = __float2bfloat16(v.z); h1.y = __float2bfloat16(v.w);
        l0.x = __float2bfloat16(v.x - __bfloat162float(h0.x));
        l0.y = __float2bfloat16(v.y - __bfloat162float(h0.y));
        l1.x = __float2bfloat16(v.z - __bfloat162float(h1.x));
        l1.y = __float2bfloat16(v.w - __bfloat162float(h1.y));
        ((__nv_bfloat162*)(hi + 4 * j))[0] = h0;
        ((__nv_bfloat162*)(hi + 4 * j))[1] = h1;
        ((__nv_bfloat162*)(lo + 4 * j))[0] = l0;
        ((__nv_bfloat162*)(lo + 4 * j))[1] = l1;
    }
}

// ---------------- shared memory layouts ----------------
#define SAW 80     // bytes per smem row (40 halves): 16B aligned, ldmatrix conflict-free
#define G1_AH  0
#define G1_AL  10240
#define G1_B1H 20480
#define G1_B1L 25600
#define G1_B3H 30720
#define G1_B3L 35840
#define G1_STAGE 40960
#define G1_SMEM (2*G1_STAGE)
#define G2_AH  0
#define G2_AL  10240
#define G2_BH  20480
#define G2_BL  30720
#define G2_STAGE 40960
#define G2_SMEM (2*G2_STAGE)

// ---------------- GEMM1: hidden = silu(x@w1^T) * (x@w3^T), bf16x3 -----------
__device__ __forceinline__ void g1_load(uint32_t st,
        const bf16* Ah, const bf16* Al,
        const bf16* B1h, const bf16* B1l,
        const bf16* B3h, const bf16* B3l, int kt, int tid) {
#pragma unroll
    for (int i = 0; i < 2; i++) {
        int idx = tid + i * 256;
        int m = idx >> 2, c = idx & 3;
        cp16(st + G1_AH + m * SAW + c * 16, Ah + (size_t)m * DIM + kt + c * 8);
        cp16(st + G1_AL + m * SAW + c * 16, Al + (size_t)m * DIM + kt + c * 8);
    }
    {
        int n = tid >> 2, c = tid & 3;
        cp16(st + G1_B1H + n * SAW + c * 16, B1h + (size_t)n * DIM + kt + c * 8);
        cp16(st + G1_B1L + n * SAW + c * 16, B1l + (size_t)n * DIM + kt + c * 8);
        cp16(st + G1_B3H + n * SAW + c * 16, B3h + (size_t)n * DIM + kt + c * 8);
        cp16(st + G1_B3L + n * SAW + c * 16, B3l + (size_t)n * DIM + kt + c * 8);
    }
}

__global__ __launch_bounds__(256, 1) void gemm1_mma() {
    int e = blockIdx.z;
    int m0blk = blockIdx.y * 128;
    if (m0blk >= g_cntpad[e]) return;
    int row0 = g_offsets[e] + m0blk;
    int n0 = blockIdx.x * 64;

    extern __shared__ __align__(16) char smem[];
    uint32_t sb = smem_u32(smem);
    int tid = threadIdx.x, lane = tid & 31, warp = tid >> 5;
    int gr = lane >> 2, gc2 = (lane & 3) * 2;
    int wm = (warp & 3) * 32;
    int wn = (warp >> 2) * 32;

    const bf16* Ah  = g_xh  + (size_t)row0 * DIM;
    const bf16* Al  = g_xl  + (size_t)row0 * DIM;
    const size_t wb = ((size_t)e * HID + n0) * DIM;
    const bf16* B1h = g_w1h + wb;
    const bf16* B1l = g_w1l + wb;
    const bf16* B3h = g_w3h + wb;
    const bf16* B3l = g_w3l + wb;

    float acc1[2][4][4], acc3[2][4][4];
#pragma unroll
    for (int i = 0; i < 2; i++)
#pragma unroll
        for (int j = 0; j < 4; j++)
#pragma unroll
            for (int q = 0; q < 4; q++) { acc1[i][j][q] = 0.f; acc3[i][j][q] = 0.f; }

    // ldmatrix per-lane address components
    uint32_t aRow = (lane & 15);                 // + wm + i*16
    uint32_t aK16 = (lane >> 4) * 16;            // k-halves select
    uint32_t bTile = lane >> 3;                  // 0..3
    uint32_t bRow = (bTile >> 1) * 8 + (lane & 7);   // + wn + jp*16
    uint32_t bK16 = (bTile & 1) * 16;

    const int NK = DIM / 32;   // 32
    g1_load(sb, Ah, Al, B1h, B1l, B3h, B3l, 0, tid);
    cp_commit();

#pragma unroll 1
    for (int kc = 0; kc < NK; kc++) {
        cp_wait0();
        __syncthreads();
        if (kc + 1 < NK) {
            g1_load(sb + ((kc + 1) & 1) * G1_STAGE, Ah, Al, B1h, B1l, B3h, B3l,
                    (kc + 1) * 32, tid);
            cp_commit();
        }
        uint32_t stv = sb + (kc & 1) * G1_STAGE;
#pragma unroll
        for (int p = 0; p < 3; p++) {
            uint32_t aOff  = stv + (p == 2 ? G1_AL  : G1_AH);
            uint32_t b1Off = stv + (p == 1 ? G1_B1L : G1_B1H);
            uint32_t b3Off = stv + (p == 1 ? G1_B3L : G1_B3H);
#pragma unroll
            for (int ks = 0; ks < 2; ks++) {
                int k0b = ks * 32;  // bytes (16 halves)
                uint32_t a[2][4];
#pragma unroll
                for (int i = 0; i < 2; i++)
                    ldm_x4(a[i][0], a[i][1], a[i][2], a[i][3],
                           aOff + (wm + i * 16 + aRow) * SAW + k0b + aK16);
#pragma unroll
                for (int jp = 0; jp < 2; jp++) {
                    uint32_t nr = (wn + jp * 16 + bRow) * SAW + k0b + bK16;
                    uint32_t b1r[4], b3r[4];
                    ldm_x4(b1r[0], b1r[1], b1r[2], b1r[3], b1Off + nr);
                    ldm_x4(b3r[0], b3r[1], b3r[2], b3r[3], b3Off + nr);
#pragma unroll
                    for (int i = 0; i < 2; i++) {
                        mma_bf16(acc1[i][jp * 2 + 0], a[i][0], a[i][1], a[i][2], a[i][3], b1r[0], b1r[1]);
                        mma_bf16(acc1[i][jp * 2 + 1], a[i][0], a[i][1], a[i][2], a[i][3], b1r[2], b1r[3]);
                        mma_bf16(acc3[i][jp * 2 + 0], a[i][0], a[i][1], a[i][2], a[i][3], b3r[0], b3r[1]);
                        mma_bf16(acc3[i][jp * 2 + 1], a[i][0], a[i][1], a[i][2], a[i][3], b3r[2], b3r[3]);
                    }
                }
            }
        }
    }

    // epilogue: silu(h1)*h3 -> bf16 hi/lo
#pragma unroll
    for (int i = 0; i < 2; i++)
#pragma unroll
        for (int j = 0; j < 4; j++) {
            int m = wm + i * 16 + gr;
            int n = wn + j * 8 + gc2;
#pragma unroll
            for (int half = 0; half < 2; half++) {
                int mm = m + half * 8;
                float h1a = acc1[i][j][half * 2 + 0], h1b = acc1[i][j][half * 2 + 1];
                float h3a = acc3[i][j][half * 2 + 0], h3b = acc3[i][j][half * 2 + 1];
                float v0 = h3a * h1a / (1.f + __expf(-h1a));
                float v1 = h3b * h1b / (1.f + __expf(-h1b));
                size_t idx = (size_t)(row0 + mm) * HID + n0 + n;
                __nv_bfloat162 hh, ll;
                hh.x = __float2bfloat16(v0); hh.y = __float2bfloat16(v1);
                ll.x = __float2bfloat16(v0 - __bfloat162float(hh.x));
                ll.y = __float2bfloat16(v1 - __bfloat162float(hh.y));
                *(__nv_bfloat162*)(g_hh + idx) = hh;
                *(__nv_bfloat162*)(g_hl + idx) = ll;
            }
        }
}

// ---------------- GEMM2: y = hidden @ w2^T, bf16x3 --------------------------
__device__ __forceinline__ void g2_load(uint32_t st,
        const bf16* Ah, const bf16* Al,
        const bf16* Bh, const bf16* Bl, int kt, int tid) {
#pragma unroll
    for (int i = 0; i < 2; i++) {
        int idx = tid + i * 256;
        int m = idx >> 2, c = idx & 3;
        cp16(st + G2_AH + m * SAW + c * 16, Ah + (size_t)m * HID + kt + c * 8);
        cp16(st + G2_AL + m * SAW + c * 16, Al + (size_t)m * HID + kt + c * 8);
        cp16(st + G2_BH + m * SAW + c * 16, Bh + (size_t)m * HID + kt + c * 8);
        cp16(st + G2_BL + m * SAW + c * 16, Bl + (size_t)m * HID + kt + c * 8);
    }
}

__global__ __launch_bounds__(256, 1) void gemm2_mma() {
    int e = blockIdx.z;
    int m0blk = blockIdx.y * 128;
    if (m0blk >= g_cntpad[e]) return;
    int row0 = g_offsets[e] + m0blk;
    int n0 = blockIdx.x * 128;

    extern __shared__ __align__(16) char smem[];
    uint32_t sb = smem_u32(smem);
    int tid = threadIdx.x, lane = tid & 31, warp = tid >> 5;
    int gr = lane >> 2, gc2 = (lane & 3) * 2;
    int wm = (warp & 3) * 32;
    int wn = (warp >> 2) * 64;

    const bf16* Ah = g_hh + (size_t)row0 * HID;
    const bf16* Al = g_hl + (size_t)row0 * HID;
    const size_t wb = ((size_t)e * DIM + n0) * HID;
    const bf16* Bh = g_w2h + wb;
    const bf16* Bl = g_w2l + wb;

    float acc[2][8][4];
#pragma unroll
    for (int i = 0; i < 2; i++)
#pragma unroll
        for (int j = 0; j < 8; j++)
#pragma unroll
            for (int q = 0; q < 4; q++) acc[i][j][q] = 0.f;

    uint32_t aRow = (lane & 15);
    uint32_t aK16 = (lane >> 4) * 16;
    uint32_t bTile = lane >> 3;
    uint32_t bRow = (bTile >> 1) * 8 + (lane & 7);
    uint32_t bK16 = (bTile & 1) * 16;

    const int NK = HID / 32;   // 64
    g2_load(sb, Ah, Al, Bh, Bl, 0, tid);
    cp_commit();

#pragma unroll 1
    for (int kc = 0; kc < NK; kc++) {
        cp_wait0();
        __syncthreads();
        if (kc + 1 < NK) {
            g2_load(sb + ((kc + 1) & 1) * G2_STAGE, Ah, Al, Bh, Bl, (kc + 1) * 32, tid);
            cp_commit();
        }
        uint32_t stv = sb + (kc & 1) * G2_STAGE;
#pragma unroll
        for (int p = 0; p < 3; p++) {
            uint32_t aOff = stv + (p == 2 ? G2_AL : G2_AH);
            uint32_t bOff = stv + (p == 1 ? G2_BL : G2_BH);
#pragma unroll
            for (int ks = 0; ks < 2; ks++) {
                int k0b = ks * 32;
                uint32_t a[2][4];
#pragma unroll
                for (int i = 0; i < 2; i++)
                    ldm_x4(a[i][0], a[i][1], a[i][2], a[i][3],
                           aOff + (wm + i * 16 + aRow) * SAW + k0b + aK16);
#pragma unroll
                for (int jp = 0; jp < 4; jp++) {
                    uint32_t br[4];
                    ldm_x4(br[0], br[1], br[2], br[3],
                           bOff + (wn + jp * 16 + bRow) * SAW + k0b + bK16);
#pragma unroll
                    for (int i = 0; i < 2; i++) {
                        mma_bf16(acc[i][jp * 2 + 0], a[i][0], a[i][1], a[i][2], a[i][3], br[0], br[1]);
                        mma_bf16(acc[i][jp * 2 + 1], a[i][0], a[i][1], a[i][2], a[i][3], br[2], br[3]);
                    }
                }
            }
        }
    }

#pragma unroll
    for (int i = 0; i < 2; i++)
#pragma unroll
        for (int j = 0; j < 8; j++) {
            int m = wm + i * 16 + gr;
            int n = wn + j * 8 + gc2;
#pragma unroll
            for (int half = 0; half < 2; half++) {
                int mm = m + half * 8;
                float2 v = make_float2(acc[i][j][half * 2 + 0], acc[i][j][half * 2 + 1]);
                *(float2*)(g_y + (size_t)(row0 + mm) * DIM + n0 + n) = v;
            }
        }
}

// ---------------- launch 5: combine ----------------
__global__ void combine_kernel(float* __restrict__ out) {
    int idx = blockIdx.x * blockDim.x + threadIdx.x;
    if (idx >= T_TOK * DIM / 4) return;
    int t = idx / (DIM / 4);
    int d4 = idx - t * (DIM / 4);
    float w0 = g_gwt[t * 2 + 0], w1 = g_gwt[t * 2 + 1];
    const float4 y0 = *(const float4*)(g_y + (size_t)g_rowOf[t * 2 + 0] * DIM + d4 * 4);
    const float4 y1 = *(const float4*)(g_y + (size_t)g_rowOf[t * 2 + 1] * DIM + d4 * 4);
    float4 o;
    o.x = w0 * y0.x + w1 * y1.x;
    o.y = w0 * y0.y + w1 * y1.y;
    o.z = w0 * y0.z + w1 * y1.z;
    o.w = w0 * y0.w + w1 * y1.w;
    ((float4*)out)[idx] = o;
}

// ---------------- launch ----------------
extern "C" void kernel_launch(void* const* d_in, const int* in_sizes, int n_in,
                              void* d_out, int out_size) {
    const float* x  = (const float*)d_in[0];
    const float* gw = (const float*)d_in[1];
    const float* w1 = (const float*)d_in[2];
    const float* w3 = (const float*)d_in[3];
    const float* w2 = (const float*)d_in[4];
    float* out = (float*)d_out;

    cudaFuncSetAttribute(gemm1_mma, cudaFuncAttributeMaxDynamicSharedMemorySize, G1_SMEM);
    cudaFuncSetAttribute(gemm2_mma, cudaFuncAttributeMaxDynamicSharedMemorySize, G2_SMEM);

    gating_kernel<<<T_TOK / 8, 256>>>(x, gw);                          // my idx 0
    scatscan_kernel<<<1, 1024>>>();                                    // 1
    prep_kernel<<<PADT + WBLK, 256>>>(x, w1, w3, w2);                  // 2
    gemm1_mma<<<dim3(HID / 64, 128, NEXP), 256, G1_SMEM>>>();          // 3 (ncu -s 5 target)
    gemm2_mma<<<dim3(DIM / 128, 128, NEXP), 256, G2_SMEM>>>();         // 4
    combine_kernel<<<(T_TOK * DIM / 4 + 255) / 256, 256>>>(out);       // 5
}

// round 6
// speedup vs baseline: 1.0340x; 1.0238x over previous
#include <cuda_runtime.h>
#include <cuda_bf16.h>
#include <math.h>
#include <stdint.h>

// ---------------- problem constants ----------------
#define T_TOK 16384
#define DIM   1024
#define HID   2048
#define NEXP  8
#define TOPK  2
#define NSLOT (T_TOK*TOPK)                 // 32768
#define PADT  (NSLOT + NEXP*128)           // 33792 padded rows

typedef __nv_bfloat16 bf16;

// ---------------- device scratch (allocation-free rule) ----------------
__device__ int   g_counts[NEXP];
__device__ int   g_cntpad[NEXP];
__device__ int   g_offsets[NEXP];
__device__ int   g_perm[PADT];
__device__ int   g_rowOf[NSLOT];
__device__ int   g_sel[NSLOT];
__device__ float g_gwt[NSLOT];

__device__ bf16  g_w1h[(size_t)NEXP*HID*DIM];
__device__ bf16  g_w1l[(size_t)NEXP*HID*DIM];
__device__ bf16  g_w3h[(size_t)NEXP*HID*DIM];
__device__ bf16  g_w3l[(size_t)NEXP*HID*DIM];
__device__ bf16  g_w2h[(size_t)NEXP*DIM*HID];
__device__ bf16  g_w2l[(size_t)NEXP*DIM*HID];
__device__ bf16  g_xh[(size_t)PADT*DIM];
__device__ bf16  g_xl[(size_t)PADT*DIM];
__device__ bf16  g_hh[(size_t)PADT*HID];
__device__ bf16  g_hl[(size_t)PADT*HID];
__device__ float g_y [(size_t)PADT*DIM];

// ---------------- helpers (base-PTX only) ----------------
__device__ __forceinline__ uint32_t smem_u32(const void* p) {
    uint32_t a;
    asm("{ .reg .u64 t; cvta.to.shared.u64 t, %1; cvt.u32.u64 %0, t; }" : "=r"(a) : "l"(p));
    return a;
}
__device__ __forceinline__ void cp16(uint32_t dst, const void* src) {
    asm volatile("cp.async.cg.shared.global [%0], [%1], 16;" :: "r"(dst), "l"(src));
}
__device__ __forceinline__ void cp_commit() {
    asm volatile("cp.async.commit_group;");
}
__device__ __forceinline__ void cp_wait0() {
    asm volatile("cp.async.wait_group 0;" ::: "memory");
}
__device__ __forceinline__ void mma_bf16(float c[4], const uint32_t a[4],
                                         uint32_t b0, uint32_t b1) {
    asm volatile(
        "mma.sync.aligned.m16n8k16.row.col.f32.bf16.bf16.f32 "
        "{%0,%1,%2,%3}, {%4,%5,%6,%7}, {%8,%9}, {%0,%1,%2,%3};"
        : "+f"(c[0]), "+f"(c[1]), "+f"(c[2]), "+f"(c[3])
        : "r"(a[0]), "r"(a[1]), "r"(a[2]), "r"(a[3]), "r"(b0), "r"(b1));
}
__device__ __forceinline__ void ldm_x4(uint32_t* r, uint32_t a) {
    asm volatile("ldmatrix.sync.aligned.m8n8.x4.shared.b16 {%0,%1,%2,%3}, [%4];"
                 : "=r"(r[0]), "=r"(r[1]), "=r"(r[2]), "=r"(r[3]) : "r"(a));
}

// ---------------- launch 0: gating (1 warp / token) ------
__global__ void gating_kernel(const float* __restrict__ x, const float* __restrict__ gw) {
    int t = (blockIdx.x * blockDim.x + threadIdx.x) >> 5;
    int lane = threadIdx.x & 31;
    if (t >= T_TOK) return;
    const float* xr = x + (size_t)t * DIM;
    float xv[DIM / 32];
#pragma unroll
    for (int i = 0; i < DIM / 32; i++) xv[i] = xr[lane + 32 * i];
    float logits[NEXP];
#pragma unroll
    for (int e = 0; e < NEXP; e++) {
        const float* g = gw + e * DIM;
        float acc = 0.f;
#pragma unroll
        for (int i = 0; i < DIM / 32; i++) acc = fmaf(xv[i], g[lane + 32 * i], acc);
#pragma unroll
        for (int o = 16; o; o >>= 1) acc += __shfl_xor_sync(0xffffffffu, acc, o);
        logits[e] = acc;
    }
    if (lane == 0) {
        int e0 = 0; float l0 = logits[0];
#pragma unroll
        for (int e = 1; e < NEXP; e++) if (logits[e] > l0) { l0 = logits[e]; e0 = e; }
        int e1 = (e0 == 0) ? 1 : 0; float l1 = logits[e1];
#pragma unroll
        for (int e = 0; e < NEXP; e++) if (e != e0 && logits[e] > l1) { l1 = logits[e]; e1 = e; }
        float p1 = __expf(l1 - l0);
        float inv = 1.f / (1.f + p1);
        g_sel[t * 2 + 0] = e0; g_sel[t * 2 + 1] = e1;
        g_gwt[t * 2 + 0] = inv; g_gwt[t * 2 + 1] = p1 * inv;
    }
}

// ---------------- launch 1: count + scan + scatter (single block) -----------
__global__ __launch_bounds__(1024) void scatscan_kernel() {
    __shared__ int scnt[NEXP];
    __shared__ int scur[NEXP];
    int tid = threadIdx.x;
    if (tid < NEXP) scnt[tid] = 0;
    __syncthreads();
    for (int idx = tid; idx < NSLOT; idx += 1024)
        atomicAdd(&scnt[g_sel[idx]], 1);
    __syncthreads();
    if (tid == 0) {
        int o = 0;
        for (int e = 0; e < NEXP; e++) {
            int c = scnt[e];
            int cp = (c + 127) & ~127;
            g_counts[e] = c;
            g_offsets[e] = o;
            g_cntpad[e] = cp;
            scur[e] = o;
            o += cp;
        }
    }
    __syncthreads();
    for (int idx = tid; idx < NSLOT; idx += 1024) {
        int e = g_sel[idx];
        int pos = atomicAdd(&scur[e], 1);
        g_perm[pos] = idx >> 1;
        g_rowOf[idx] = pos;
    }
}

// ---------------- launch 2: prep = gather(x) + weight convert ---------------
#define WQ ((size_t)NEXP*HID*DIM/4)
#define WBLK ((unsigned)((3*WQ + 255) / 256))
__global__ __launch_bounds__(256) void prep_kernel(const float* __restrict__ x,
                                                   const float* __restrict__ w1,
                                                   const float* __restrict__ w3,
                                                   const float* __restrict__ w2) {
    int b = blockIdx.x;
    if (b < PADT) {
        int row = b;
        int e = -1, r = 0;
#pragma unroll
        for (int i = 0; i < NEXP; i++) {
            int o = g_offsets[i], c = g_cntpad[i];
            if (row >= o && row < o + c) { e = i; r = row - o; }
        }
        if (e < 0) return;
        float4 v = make_float4(0.f, 0.f, 0.f, 0.f);
        if (r < g_counts[e]) {
            int tok = g_perm[row];
            v = *(const float4*)(x + (size_t)tok * DIM + threadIdx.x * 4);
        }
        size_t o = (size_t)row * DIM + threadIdx.x * 4;
        __nv_bfloat162 h0, h1, l0, l1;
        h0.x = __float2bfloat16(v.x); h0.y = __float2bfloat16(v.y);
        h1.x = __float2bfloat16(v.z); h1.y = __float2bfloat16(v.w);
        l0.x = __float2bfloat16(v.x - __bfloat162float(h0.x));
        l0.y = __float2bfloat16(v.y - __bfloat162float(h0.y));
        l1.x = __float2bfloat16(v.z - __bfloat162float(h1.x));
        l1.y = __float2bfloat16(v.w - __bfloat162float(h1.y));
        ((__nv_bfloat162*)(g_xh + o))[0] = h0; ((__nv_bfloat162*)(g_xh + o))[1] = h1;
        ((__nv_bfloat162*)(g_xl + o))[0] = l0; ((__nv_bfloat162*)(g_xl + o))[1] = l1;
    } else {
        size_t i = (size_t)(b - PADT) * 256 + threadIdx.x;
        if (i >= 3 * WQ) return;
        const float* src; bf16 *hi, *lo; size_t j;
        if (i < WQ)          { src = w1; hi = g_w1h; lo = g_w1l; j = i; }
        else if (i < 2 * WQ) { src = w3; hi = g_w3h; lo = g_w3l; j = i - WQ; }
        else                 { src = w2; hi = g_w2h; lo = g_w2l; j = i - 2 * WQ; }
        float4 v = ((const float4*)src)[j];
        __nv_bfloat162 h0, h1, l0, l1;
        h0.x = __float2bfloat16(v.x); h0.y = __float2bfloat16(v.y);
        h1.x = __float2bfloat16(v.z); h1.y = __float2bfloat16(v.w);
        l0.x = __float2bfloat16(v.x - __bfloat162float(h0.x));
        l0.y = __float2bfloat16(v.y - __bfloat162float(h0.y));
        l1.x = __float2bfloat16(v.z - __bfloat162float(h1.x));
        l1.y = __float2bfloat16(v.w - __bfloat162float(h1.y));
        ((__nv_bfloat162*)(hi + 4 * j))[0] = h0;
        ((__nv_bfloat162*)(hi + 4 * j))[1] = h1;
        ((__nv_bfloat162*)(lo + 4 * j))[0] = l0;
        ((__nv_bfloat162*)(lo + 4 * j))[1] = l1;
    }
}

// ---------------- shared memory layouts ----------------
#define SAW 80
#define G1_AH  0
#define G1_AL  10240
#define G1_B1H 20480
#define G1_B1L 25600
#define G1_B3H 30720
#define G1_B3L 35840
#define G1_STAGE 40960
#define G1_SMEM (2*G1_STAGE)
#define G2_AH  0
#define G2_AL  10240
#define G2_BH  20480
#define G2_BL  30720
#define G2_STAGE 40960
#define G2_SMEM (2*G2_STAGE)

// ---------------- GEMM1: hidden = silu(x@w1^T) * (x@w3^T), bf16x3 -----------
__device__ __forceinline__ void g1_load(uint32_t st,
        const bf16* Ah, const bf16* Al,
        const bf16* B1h, const bf16* B1l,
        const bf16* B3h, const bf16* B3l, int kt, int tid) {
#pragma unroll
    for (int i = 0; i < 2; i++) {
        int idx = tid + i * 256;
        int m = idx >> 2, c = idx & 3;
        cp16(st + G1_AH + m * SAW + c * 16, Ah + (size_t)m * DIM + kt + c * 8);
        cp16(st + G1_AL + m * SAW + c * 16, Al + (size_t)m * DIM + kt + c * 8);
    }
    {
        int n = tid >> 2, c = tid & 3;
        cp16(st + G1_B1H + n * SAW + c * 16, B1h + (size_t)n * DIM + kt + c * 8);
        cp16(st + G1_B1L + n * SAW + c * 16, B1l + (size_t)n * DIM + kt + c * 8);
        cp16(st + G1_B3H + n * SAW + c * 16, B3h + (size_t)n * DIM + kt + c * 8);
        cp16(st + G1_B3L + n * SAW + c * 16, B3l + (size_t)n * DIM + kt + c * 8);
    }
}

__global__ __launch_bounds__(256, 1) void gemm1_mma() {
    int e = blockIdx.z;
    int m0blk = blockIdx.y * 128;
    if (m0blk >= g_cntpad[e]) return;
    int row0 = g_offsets[e] + m0blk;
    int n0 = blockIdx.x * 64;

    extern __shared__ __align__(16) char smem[];
    uint32_t sb = smem_u32(smem);
    int tid = threadIdx.x, lane = tid & 31, warp = tid >> 5;
    int gr = lane >> 2, gc2 = (lane & 3) * 2;
    int wm = (warp & 3) * 32;
    int wn = (warp >> 2) * 32;

    const bf16* Ah  = g_xh  + (size_t)row0 * DIM;
    const bf16* Al  = g_xl  + (size_t)row0 * DIM;
    const size_t wb = ((size_t)e * HID + n0) * DIM;
    const bf16* B1h = g_w1h + wb;
    const bf16* B1l = g_w1l + wb;
    const bf16* B3h = g_w3h + wb;
    const bf16* B3l = g_w3l + wb;

    float acc1[2][4][4], acc3[2][4][4];
#pragma unroll
    for (int i = 0; i < 2; i++)
#pragma unroll
        for (int j = 0; j < 4; j++)
#pragma unroll
            for (int q = 0; q < 4; q++) { acc1[i][j][q] = 0.f; acc3[i][j][q] = 0.f; }

    // ldmatrix per-lane address components
    uint32_t aAddr = (lane & 15) * SAW + (lane >> 4) * 16;                      // + wm/i row, +k
    uint32_t bAddr = (((lane >> 4) & 1) * 8 + (lane & 7)) * SAW + ((lane >> 3) & 1) * 16;

    const int NK = DIM / 32;   // 32
    g1_load(sb, Ah, Al, B1h, B1l, B3h, B3l, 0, tid);
    cp_commit();

#pragma unroll 1
    for (int kc = 0; kc < NK; kc++) {
        cp_wait0();
        __syncthreads();
        if (kc + 1 < NK) {
            g1_load(sb + ((kc + 1) & 1) * G1_STAGE, Ah, Al, B1h, B1l, B3h, B3l,
                    (kc + 1) * 32, tid);
            cp_commit();
        }
        uint32_t stv = sb + (kc & 1) * G1_STAGE;
#pragma unroll
        for (int ks = 0; ks < 2; ks++) {
            uint32_t k0b = ks * 32;
            // ---- load ALL fragments for this k16 once ----
            uint32_t ah[2][4], al[2][4];
#pragma unroll
            for (int i = 0; i < 2; i++) {
                uint32_t ra = (wm + i * 16) * SAW + aAddr + k0b;
                ldm_x4(ah[i], stv + G1_AH + ra);
                ldm_x4(al[i], stv + G1_AL + ra);
            }
            uint32_t b1h[2][4], b1l[2][4], b3h[2][4], b3l[2][4];
#pragma unroll
            for (int jp = 0; jp < 2; jp++) {
                uint32_t rb = (wn + jp * 16) * SAW + bAddr + k0b;
                ldm_x4(b1h[jp], stv + G1_B1H + rb);
                ldm_x4(b1l[jp], stv + G1_B1L + rb);
                ldm_x4(b3h[jp], stv + G1_B3H + rb);
                ldm_x4(b3l[jp], stv + G1_B3L + rb);
            }
            // ---- all 48 MMAs from registers ----
#pragma unroll
            for (int i = 0; i < 2; i++)
#pragma unroll
                for (int jp = 0; jp < 2; jp++) {
                    int j0 = jp * 2, j1 = jp * 2 + 1;
                    mma_bf16(acc1[i][j0], ah[i], b1h[jp][0], b1h[jp][1]);
                    mma_bf16(acc1[i][j1], ah[i], b1h[jp][2], b1h[jp][3]);
                    mma_bf16(acc3[i][j0], ah[i], b3h[jp][0], b3h[jp][1]);
                    mma_bf16(acc3[i][j1], ah[i], b3h[jp][2], b3h[jp][3]);
                    mma_bf16(acc1[i][j0], ah[i], b1l[jp][0], b1l[jp][1]);
                    mma_bf16(acc1[i][j1], ah[i], b1l[jp][2], b1l[jp][3]);
                    mma_bf16(acc3[i][j0], ah[i], b3l[jp][0], b3l[jp][1]);
                    mma_bf16(acc3[i][j1], ah[i], b3l[jp][2], b3l[jp][3]);
                    mma_bf16(acc1[i][j0], al[i], b1h[jp][0], b1h[jp][1]);
                    mma_bf16(acc1[i][j1], al[i], b1h[jp][2], b1h[jp][3]);
                    mma_bf16(acc3[i][j0], al[i], b3h[jp][0], b3h[jp][1]);
                    mma_bf16(acc3[i][j1], al[i], b3h[jp][2], b3h[jp][3]);
                }
        }
    }

    // epilogue: silu(h1)*h3 -> bf16 hi/lo
#pragma unroll
    for (int i = 0; i < 2; i++)
#pragma unroll
        for (int j = 0; j < 4; j++) {
            int m = wm + i * 16 + gr;
            int n = wn + j * 8 + gc2;
#pragma unroll
            for (int half = 0; half < 2; half++) {
                int mm = m + half * 8;
                float h1a = acc1[i][j][half * 2 + 0], h1b = acc1[i][j][half * 2 + 1];
                float h3a = acc3[i][j][half * 2 + 0], h3b = acc3[i][j][half * 2 + 1];
                float v0 = h3a * h1a / (1.f + __expf(-h1a));
                float v1 = h3b * h1b / (1.f + __expf(-h1b));
                size_t idx = (size_t)(row0 + mm) * HID + n0 + n;
                __nv_bfloat162 hh, ll;
                hh.x = __float2bfloat16(v0); hh.y = __float2bfloat16(v1);
                ll.x = __float2bfloat16(v0 - __bfloat162float(hh.x));
                ll.y = __float2bfloat16(v1 - __bfloat162float(hh.y));
                *(__nv_bfloat162*)(g_hh + idx) = hh;
                *(__nv_bfloat162*)(g_hl + idx) = ll;
            }
        }
}

// ---------------- GEMM2: y = hidden @ w2^T, bf16x3 --------------------------
__device__ __forceinline__ void g2_load(uint32_t st,
        const bf16* Ah, const bf16* Al,
        const bf16* Bh, const bf16* Bl, int kt, int tid) {
#pragma unroll
    for (int i = 0; i < 2; i++) {
        int idx = tid + i * 256;
        int m = idx >> 2, c = idx & 3;
        cp16(st + G2_AH + m * SAW + c * 16, Ah + (size_t)m * HID + kt + c * 8);
        cp16(st + G2_AL + m * SAW + c * 16, Al + (size_t)m * HID + kt + c * 8);
        cp16(st + G2_BH + m * SAW + c * 16, Bh + (size_t)m * HID + kt + c * 8);
        cp16(st + G2_BL + m * SAW + c * 16, Bl + (size_t)m * HID + kt + c * 8);
    }
}

__global__ __launch_bounds__(256, 1) void gemm2_mma() {
    int e = blockIdx.z;
    int m0blk = blockIdx.y * 128;
    if (m0blk >= g_cntpad[e]) return;
    int row0 = g_offsets[e] + m0blk;
    int n0 = blockIdx.x * 128;

    extern __shared__ __align__(16) char smem[];
    uint32_t sb = smem_u32(smem);
    int tid = threadIdx.x, lane = tid & 31, warp = tid >> 5;
    int gr = lane >> 2, gc2 = (lane & 3) * 2;
    int wm = (warp & 3) * 32;
    int wn = (warp >> 2) * 64;

    const bf16* Ah = g_hh + (size_t)row0 * HID;
    const bf16* Al = g_hl + (size_t)row0 * HID;
    const size_t wb = ((size_t)e * DIM + n0) * HID;
    const bf16* Bh = g_w2h + wb;
    const bf16* Bl = g_w2l + wb;

    float acc[2][8][4];
#pragma unroll
    for (int i = 0; i < 2; i++)
#pragma unroll
        for (int j = 0; j < 8; j++)
#pragma unroll
            for (int q = 0; q < 4; q++) acc[i][j][q] = 0.f;

    uint32_t aAddr = (lane & 15) * SAW + (lane >> 4) * 16;
    uint32_t bAddr = (((lane >> 4) & 1) * 8 + (lane & 7)) * SAW + ((lane >> 3) & 1) * 16;

    const int NK = HID / 32;   // 64
    g2_load(sb, Ah, Al, Bh, Bl, 0, tid);
    cp_commit();

#pragma unroll 1
    for (int kc = 0; kc < NK; kc++) {
        cp_wait0();
        __syncthreads();
        if (kc + 1 < NK) {
            g2_load(sb + ((kc + 1) & 1) * G2_STAGE, Ah, Al, Bh, Bl, (kc + 1) * 32, tid);
            cp_commit();
        }
        uint32_t stv = sb + (kc & 1) * G2_STAGE;
#pragma unroll
        for (int ks = 0; ks < 2; ks++) {
            uint32_t k0b = ks * 32;
            uint32_t ah[2][4], al[2][4];
#pragma unroll
            for (int i = 0; i < 2; i++) {
                uint32_t ra = (wm + i * 16) * SAW + aAddr + k0b;
                ldm_x4(ah[i], stv + G2_AH + ra);
                ldm_x4(al[i], stv + G2_AL + ra);
            }
            uint32_t bh[4][4], bl[4][4];
#pragma unroll
            for (int jp = 0; jp < 4; jp++) {
                uint32_t rb = (wn + jp * 16) * SAW + bAddr + k0b;
                ldm_x4(bh[jp], stv + G2_BH + rb);
                ldm_x4(bl[jp], stv + G2_BL + rb);
            }
#pragma unroll
            for (int i = 0; i < 2; i++)
#pragma unroll
                for (int jp = 0; jp < 4; jp++) {
                    int j0 = jp * 2, j1 = jp * 2 + 1;
                    mma_bf16(acc[i][j0], ah[i], bh[jp][0], bh[jp][1]);
                    mma_bf16(acc[i][j1], ah[i], bh[jp][2], bh[jp][3]);
                    mma_bf16(acc[i][j0], ah[i], bl[jp][0], bl[jp][1]);
                    mma_bf16(acc[i][j1], ah[i], bl[jp][2], bl[jp][3]);
                    mma_bf16(acc[i][j0], al[i], bh[jp][0], bh[jp][1]);
                    mma_bf16(acc[i][j1], al[i], bh[jp][2], bh[jp][3]);
                }
        }
    }

#pragma unroll
    for (int i = 0; i < 2; i++)
#pragma unroll
        for (int j = 0; j < 8; j++) {
            int m = wm + i * 16 + gr;
            int n = wn + j * 8 + gc2;
#pragma unroll
            for (int half = 0; half < 2; half++) {
                int mm = m + half * 8;
                float2 v = make_float2(acc[i][j][half * 2 + 0], acc[i][j][half * 2 + 1]);
                *(float2*)(g_y + (size_t)(row0 + mm) * DIM + n0 + n) = v;
            }
        }
}

// ---------------- launch 5: combine ----------------
__global__ void combine_kernel(float* __restrict__ out) {
    int idx = blockIdx.x * blockDim.x + threadIdx.x;
    if (idx >= T_TOK * DIM / 4) return;
    int t = idx / (DIM / 4);
    int d4 = idx - t * (DIM / 4);
    float w0 = g_gwt[t * 2 + 0], w1 = g_gwt[t * 2 + 1];
    const float4 y0 = *(const float4*)(g_y + (size_t)g_rowOf[t * 2 + 0] * DIM + d4 * 4);
    const float4 y1 = *(const float4*)(g_y + (size_t)g_rowOf[t * 2 + 1] * DIM + d4 * 4);
    float4 o;
    o.x = w0 * y0.x + w1 * y1.x;
    o.y = w0 * y0.y + w1 * y1.y;
    o.z = w0 * y0.z + w1 * y1.z;
    o.w = w0 * y0.w + w1 * y1.w;
    ((float4*)out)[idx] = o;
}

// ---------------- launch ----------------
extern "C" void kernel_launch(void* const* d_in, const int* in_sizes, int n_in,
                              void* d_out, int out_size) {
    const float* x  = (const float*)d_in[0];
    const float* gw = (const float*)d_in[1];
    const float* w1 = (const float*)d_in[2];
    const float* w3 = (const float*)d_in[3];
    const float* w2 = (const float*)d_in[4];
    float* out = (float*)d_out;

    cudaFuncSetAttribute(gemm1_mma, cudaFuncAttributeMaxDynamicSharedMemorySize, G1_SMEM);
    cudaFuncSetAttribute(gemm2_mma, cudaFuncAttributeMaxDynamicSharedMemorySize, G2_SMEM);

    gating_kernel<<<T_TOK / 8, 256>>>(x, gw);                          // 0
    scatscan_kernel<<<1, 1024>>>();                                    // 1
    prep_kernel<<<PADT + WBLK, 256>>>(x, w1, w3, w2);                  // 2
    gemm1_mma<<<dim3(HID / 64, 128, NEXP), 256, G1_SMEM>>>();          // 3 (ncu -s 5 target)
    gemm2_mma<<<dim3(DIM / 128, 128, NEXP), 256, G2_SMEM>>>();         // 4
    combine_kernel<<<(T_TOK * DIM / 4 + 255) / 256, 256>>>(out);       // 5
}

// round 7
// speedup vs baseline: 1.0357x; 1.0016x over previous
#include <cuda_runtime.h>
#include <cuda_bf16.h>
#include <math.h>
#include <stdint.h>

// ---------------- problem constants ----------------
#define T_TOK 16384
#define DIM   1024
#define HID   2048
#define NEXP  8
#define TOPK  2
#define NSLOT (T_TOK*TOPK)                 // 32768
#define PADT  (NSLOT + NEXP*128)           // 33792 padded rows

typedef __nv_bfloat16 bf16;

// ---------------- device scratch (allocation-free rule) ----------------
__device__ int   g_counts[NEXP];
__device__ int   g_cntpad[NEXP];
__device__ int   g_offsets[NEXP];
__device__ int   g_perm[PADT];
__device__ int   g_rowOf[NSLOT];
__device__ int   g_sel[NSLOT];
__device__ float g_gwt[NSLOT];

__device__ bf16  g_w1h[(size_t)NEXP*HID*DIM];
__device__ bf16  g_w1l[(size_t)NEXP*HID*DIM];
__device__ bf16  g_w3h[(size_t)NEXP*HID*DIM];
__device__ bf16  g_w3l[(size_t)NEXP*HID*DIM];
__device__ bf16  g_w2h[(size_t)NEXP*DIM*HID];
__device__ bf16  g_w2l[(size_t)NEXP*DIM*HID];
__device__ bf16  g_xh[(size_t)PADT*DIM];
__device__ bf16  g_xl[(size_t)PADT*DIM];
__device__ bf16  g_hh[(size_t)PADT*HID];
__device__ bf16  g_hl[(size_t)PADT*HID];
__device__ float g_y [(size_t)PADT*DIM];

// ---------------- helpers (base-PTX only) ----------------
__device__ __forceinline__ uint32_t smem_u32(const void* p) {
    uint32_t a;
    asm("{ .reg .u64 t; cvta.to.shared.u64 t, %1; cvt.u32.u64 %0, t; }" : "=r"(a) : "l"(p));
    return a;
}
__device__ __forceinline__ void cp16(uint32_t dst, const void* src) {
    asm volatile("cp.async.cg.shared.global [%0], [%1], 16;" :: "r"(dst), "l"(src));
}
__device__ __forceinline__ void cp_commit() {
    asm volatile("cp.async.commit_group;");
}
__device__ __forceinline__ void cp_wait0() {
    asm volatile("cp.async.wait_group 0;" ::: "memory");
}
__device__ __forceinline__ void mma_bf16(float c[4], const uint32_t a[4],
                                         uint32_t b0, uint32_t b1) {
    asm volatile(
        "mma.sync.aligned.m16n8k16.row.col.f32.bf16.bf16.f32 "
        "{%0,%1,%2,%3}, {%4,%5,%6,%7}, {%8,%9}, {%0,%1,%2,%3};"
        : "+f"(c[0]), "+f"(c[1]), "+f"(c[2]), "+f"(c[3])
        : "r"(a[0]), "r"(a[1]), "r"(a[2]), "r"(a[3]), "r"(b0), "r"(b1));
}
__device__ __forceinline__ void ldm_x4(uint32_t* r, uint32_t a) {
    asm volatile("ldmatrix.sync.aligned.m8n8.x4.shared.b16 {%0,%1,%2,%3}, [%4];"
                 : "=r"(r[0]), "=r"(r[1]), "=r"(r[2]), "=r"(r[3]) : "r"(a));
}

// ---------------- launch 0: gating (1 warp / token) ------
__global__ void gating_kernel(const float* __restrict__ x, const float* __restrict__ gw) {
    int t = (blockIdx.x * blockDim.x + threadIdx.x) >> 5;
    int lane = threadIdx.x & 31;
    if (t >= T_TOK) return;
    const float* xr = x + (size_t)t * DIM;
    float xv[DIM / 32];
#pragma unroll
    for (int i = 0; i < DIM / 32; i++) xv[i] = xr[lane + 32 * i];
    float logits[NEXP];
#pragma unroll
    for (int e = 0; e < NEXP; e++) {
        const float* g = gw + e * DIM;
        float acc = 0.f;
#pragma unroll
        for (int i = 0; i < DIM / 32; i++) acc = fmaf(xv[i], g[lane + 32 * i], acc);
#pragma unroll
        for (int o = 16; o; o >>= 1) acc += __shfl_xor_sync(0xffffffffu, acc, o);
        logits[e] = acc;
    }
    if (lane == 0) {
        int e0 = 0; float l0 = logits[0];
#pragma unroll
        for (int e = 1; e < NEXP; e++) if (logits[e] > l0) { l0 = logits[e]; e0 = e; }
        int e1 = (e0 == 0) ? 1 : 0; float l1 = logits[e1];
#pragma unroll
        for (int e = 0; e < NEXP; e++) if (e != e0 && logits[e] > l1) { l1 = logits[e]; e1 = e; }
        float p1 = __expf(l1 - l0);
        float inv = 1.f / (1.f + p1);
        g_sel[t * 2 + 0] = e0; g_sel[t * 2 + 1] = e1;
        g_gwt[t * 2 + 0] = inv; g_gwt[t * 2 + 1] = p1 * inv;
    }
}

// ---------------- launch 1: count + scan + scatter (single block) -----------
__global__ __launch_bounds__(1024) void scatscan_kernel() {
    __shared__ int scnt[NEXP];
    __shared__ int scur[NEXP];
    int tid = threadIdx.x;
    if (tid < NEXP) scnt[tid] = 0;
    __syncthreads();
    for (int idx = tid; idx < NSLOT; idx += 1024)
        atomicAdd(&scnt[g_sel[idx]], 1);
    __syncthreads();
    if (tid == 0) {
        int o = 0;
        for (int e = 0; e < NEXP; e++) {
            int c = scnt[e];
            int cp = (c + 127) & ~127;
            g_counts[e] = c;
            g_offsets[e] = o;
            g_cntpad[e] = cp;
            scur[e] = o;
            o += cp;
        }
    }
    __syncthreads();
    for (int idx = tid; idx < NSLOT; idx += 1024) {
        int e = g_sel[idx];
        int pos = atomicAdd(&scur[e], 1);
        g_perm[pos] = idx >> 1;
        g_rowOf[idx] = pos;
    }
}

// ---------------- launch 2: prep = gather(x) + weight convert ---------------
#define WQ ((size_t)NEXP*HID*DIM/4)
#define WBLK ((unsigned)((3*WQ + 255) / 256))
__global__ __launch_bounds__(256) void prep_kernel(const float* __restrict__ x,
                                                   const float* __restrict__ w1,
                                                   const float* __restrict__ w3,
                                                   const float* __restrict__ w2) {
    int b = blockIdx.x;
    if (b < PADT) {
        int row = b;
        int e = -1, r = 0;
#pragma unroll
        for (int i = 0; i < NEXP; i++) {
            int o = g_offsets[i], c = g_cntpad[i];
            if (row >= o && row < o + c) { e = i; r = row - o; }
        }
        if (e < 0) return;
        float4 v = make_float4(0.f, 0.f, 0.f, 0.f);
        if (r < g_counts[e]) {
            int tok = g_perm[row];
            v = *(const float4*)(x + (size_t)tok * DIM + threadIdx.x * 4);
        }
        size_t o = (size_t)row * DIM + threadIdx.x * 4;
        __nv_bfloat162 h0, h1, l0, l1;
        h0.x = __float2bfloat16(v.x); h0.y = __float2bfloat16(v.y);
        h1.x = __float2bfloat16(v.z); h1.y = __float2bfloat16(v.w);
        l0.x = __float2bfloat16(v.x - __bfloat162float(h0.x));
        l0.y = __float2bfloat16(v.y - __bfloat162float(h0.y));
        l1.x = __float2bfloat16(v.z - __bfloat162float(h1.x));
        l1.y = __float2bfloat16(v.w - __bfloat162float(h1.y));
        ((__nv_bfloat162*)(g_xh + o))[0] = h0; ((__nv_bfloat162*)(g_xh + o))[1] = h1;
        ((__nv_bfloat162*)(g_xl + o))[0] = l0; ((__nv_bfloat162*)(g_xl + o))[1] = l1;
    } else {
        size_t i = (size_t)(b - PADT) * 256 + threadIdx.x;
        if (i >= 3 * WQ) return;
        const float* src; bf16 *hi, *lo; size_t j;
        if (i < WQ)          { src = w1; hi = g_w1h; lo = g_w1l; j = i; }
        else if (i < 2 * WQ) { src = w3; hi = g_w3h; lo = g_w3l; j = i - WQ; }
        else                 { src = w2; hi = g_w2h; lo = g_w2l; j = i - 2 * WQ; }
        float4 v = ((const float4*)src)[j];
        __nv_bfloat162 h0, h1, l0, l1;
        h0.x = __float2bfloat16(v.x); h0.y = __float2bfloat16(v.y);
        h1.x = __float2bfloat16(v.z); h1.y = __float2bfloat16(v.w);
        l0.x = __float2bfloat16(v.x - __bfloat162float(h0.x));
        l0.y = __float2bfloat16(v.y - __bfloat162float(h0.y));
        l1.x = __float2bfloat16(v.z - __bfloat162float(h1.x));
        l1.y = __float2bfloat16(v.w - __bfloat162float(h1.y));
        ((__nv_bfloat162*)(hi + 4 * j))[0] = h0;
        ((__nv_bfloat162*)(hi + 4 * j))[1] = h1;
        ((__nv_bfloat162*)(lo + 4 * j))[0] = l0;
        ((__nv_bfloat162*)(lo + 4 * j))[1] = l1;
    }
}

// ---------------- shared memory layouts ----------------
#define SAW 80
#define G1_AH  0
#define G1_AL  10240
#define G1_B1H 20480
#define G1_B1L 25600
#define G1_B3H 30720
#define G1_B3L 35840
#define G1_STAGE 40960
#define G1_SMEM (2*G1_STAGE)
#define G2_AH  0
#define G2_AL  10240
#define G2_BH  20480
#define G2_BL  30720
#define G2_STAGE 40960
#define G2_SMEM (2*G2_STAGE)

// ---------------- GEMM1: hidden = silu(x@w1^T) * (x@w3^T), bf16x3 -----------
__device__ __forceinline__ void g1_load(uint32_t st,
        const bf16* Ah, const bf16* Al,
        const bf16* B1h, const bf16* B1l,
        const bf16* B3h, const bf16* B3l, int kt, int tid) {
#pragma unroll
    for (int i = 0; i < 2; i++) {
        int idx = tid + i * 256;
        int m = idx >> 2, c = idx & 3;
        cp16(st + G1_AH + m * SAW + c * 16, Ah + (size_t)m * DIM + kt + c * 8);
        cp16(st + G1_AL + m * SAW + c * 16, Al + (size_t)m * DIM + kt + c * 8);
    }
    {
        int n = tid >> 2, c = tid & 3;
        cp16(st + G1_B1H + n * SAW + c * 16, B1h + (size_t)n * DIM + kt + c * 8);
        cp16(st + G1_B1L + n * SAW + c * 16, B1l + (size_t)n * DIM + kt + c * 8);
        cp16(st + G1_B3H + n * SAW + c * 16, B3h + (size_t)n * DIM + kt + c * 8);
        cp16(st + G1_B3L + n * SAW + c * 16, B3l + (size_t)n * DIM + kt + c * 8);
    }
}

__global__ __launch_bounds__(256, 1) void gemm1_mma() {
    int e = blockIdx.z;
    int m0blk = blockIdx.y * 128;
    if (m0blk >= g_cntpad[e]) return;
    int row0 = g_offsets[e] + m0blk;
    int n0 = blockIdx.x * 64;

    extern __shared__ __align__(16) char smem[];
    uint32_t sb = smem_u32(smem);
    int tid = threadIdx.x, lane = tid & 31, warp = tid >> 5;
    int gr = lane >> 2, gc2 = (lane & 3) * 2;
    int wm = (warp & 3) * 32;
    int wn = (warp >> 2) * 32;

    const bf16* Ah  = g_xh  + (size_t)row0 * DIM;
    const bf16* Al  = g_xl  + (size_t)row0 * DIM;
    const size_t wb = ((size_t)e * HID + n0) * DIM;
    const bf16* B1h = g_w1h + wb;
    const bf16* B1l = g_w1l + wb;
    const bf16* B3h = g_w3h + wb;
    const bf16* B3l = g_w3l + wb;

    float acc1[2][4][4], acc3[2][4][4];
#pragma unroll
    for (int i = 0; i < 2; i++)
#pragma unroll
        for (int j = 0; j < 4; j++)
#pragma unroll
            for (int q = 0; q < 4; q++) { acc1[i][j][q] = 0.f; acc3[i][j][q] = 0.f; }

    // ldmatrix per-lane address components
    uint32_t aAddr = (lane & 15) * SAW + (lane >> 4) * 16;                      // + wm/i row, +k
    uint32_t bAddr = (((lane >> 4) & 1) * 8 + (lane & 7)) * SAW + ((lane >> 3) & 1) * 16;

    const int NK = DIM / 32;   // 32
    g1_load(sb, Ah, Al, B1h, B1l, B3h, B3l, 0, tid);
    cp_commit();

#pragma unroll 1
    for (int kc = 0; kc < NK; kc++) {
        cp_wait0();
        __syncthreads();
        if (kc + 1 < NK) {
            g1_load(sb + ((kc + 1) & 1) * G1_STAGE, Ah, Al, B1h, B1l, B3h, B3l,
                    (kc + 1) * 32, tid);
            cp_commit();
        }
        uint32_t stv = sb + (kc & 1) * G1_STAGE;
#pragma unroll
        for (int ks = 0; ks < 2; ks++) {
            uint32_t k0b = ks * 32;
            // ---- load ALL fragments for this k16 once ----
            uint32_t ah[2][4], al[2][4];
#pragma unroll
            for (int i = 0; i < 2; i++) {
                uint32_t ra = (wm + i * 16) * SAW + aAddr + k0b;
                ldm_x4(ah[i], stv + G1_AH + ra);
                ldm_x4(al[i], stv + G1_AL + ra);
            }
            uint32_t b1h[2][4], b1l[2][4], b3h[2][4], b3l[2][4];
#pragma unroll
            for (int jp = 0; jp < 2; jp++) {
                uint32_t rb = (wn + jp * 16) * SAW + bAddr + k0b;
                ldm_x4(b1h[jp], stv + G1_B1H + rb);
                ldm_x4(b1l[jp], stv + G1_B1L + rb);
                ldm_x4(b3h[jp], stv + G1_B3H + rb);
                ldm_x4(b3l[jp], stv + G1_B3L + rb);
            }
            // ---- all 48 MMAs from registers ----
#pragma unroll
            for (int i = 0; i < 2; i++)
#pragma unroll
                for (int jp = 0; jp < 2; jp++) {
                    int j0 = jp * 2, j1 = jp * 2 + 1;
                    mma_bf16(acc1[i][j0], ah[i], b1h[jp][0], b1h[jp][1]);
                    mma_bf16(acc1[i][j1], ah[i], b1h[jp][2], b1h[jp][3]);
                    mma_bf16(acc3[i][j0], ah[i], b3h[jp][0], b3h[jp][1]);
                    mma_bf16(acc3[i][j1], ah[i], b3h[jp][2], b3h[jp][3]);
                    mma_bf16(acc1[i][j0], ah[i], b1l[jp][0], b1l[jp][1]);
                    mma_bf16(acc1[i][j1], ah[i], b1l[jp][2], b1l[jp][3]);
                    mma_bf16(acc3[i][j0], ah[i], b3l[jp][0], b3l[jp][1]);
                    mma_bf16(acc3[i][j1], ah[i], b3l[jp][2], b3l[jp][3]);
                    mma_bf16(acc1[i][j0], al[i], b1h[jp][0], b1h[jp][1]);
                    mma_bf16(acc1[i][j1], al[i], b1h[jp][2], b1h[jp][3]);
                    mma_bf16(acc3[i][j0], al[i], b3h[jp][0], b3h[jp][1]);
                    mma_bf16(acc3[i][j1], al[i], b3h[jp][2], b3h[jp][3]);
                }
        }
    }

    // epilogue: silu(h1)*h3 -> bf16 hi/lo
#pragma unroll
    for (int i = 0; i < 2; i++)
#pragma unroll
        for (int j = 0; j < 4; j++) {
            int m = wm + i * 16 + gr;
            int n = wn + j * 8 + gc2;
#pragma unroll
            for (int half = 0; half < 2; half++) {
                int mm = m + half * 8;
                float h1a = acc1[i][j][half * 2 + 0], h1b = acc1[i][j][half * 2 + 1];
                float h3a = acc3[i][j][half * 2 + 0], h3b = acc3[i][j][half * 2 + 1];
                float v0 = h3a * h1a / (1.f + __expf(-h1a));
                float v1 = h3b * h1b / (1.f + __expf(-h1b));
                size_t idx = (size_t)(row0 + mm) * HID + n0 + n;
                __nv_bfloat162 hh, ll;
                hh.x = __float2bfloat16(v0); hh.y = __float2bfloat16(v1);
                ll.x = __float2bfloat16(v0 - __bfloat162float(hh.x));
                ll.y = __float2bfloat16(v1 - __bfloat162float(hh.y));
                *(__nv_bfloat162*)(g_hh + idx) = hh;
                *(__nv_bfloat162*)(g_hl + idx) = ll;
            }
        }
}

// ---------------- GEMM2: y = hidden @ w2^T, bf16x3 --------------------------
__device__ __forceinline__ void g2_load(uint32_t st,
        const bf16* Ah, const bf16* Al,
        const bf16* Bh, const bf16* Bl, int kt, int tid) {
#pragma unroll
    for (int i = 0; i < 2; i++) {
        int idx = tid + i * 256;
        int m = idx >> 2, c = idx & 3;
        cp16(st + G2_AH + m * SAW + c * 16, Ah + (size_t)m * HID + kt + c * 8);
        cp16(st + G2_AL + m * SAW + c * 16, Al + (size_t)m * HID + kt + c * 8);
        cp16(st + G2_BH + m * SAW + c * 16, Bh + (size_t)m * HID + kt + c * 8);
        cp16(st + G2_BL + m * SAW + c * 16, Bl + (size_t)m * HID + kt + c * 8);
    }
}

__global__ __launch_bounds__(256, 1) void gemm2_mma() {
    int e = blockIdx.z;
    int m0blk = blockIdx.y * 128;
    if (m0blk >= g_cntpad[e]) return;
    int row0 = g_offsets[e] + m0blk;
    int n0 = blockIdx.x * 128;

    extern __shared__ __align__(16) char smem[];
    uint32_t sb = smem_u32(smem);
    int tid = threadIdx.x, lane = tid & 31, warp = tid >> 5;
    int gr = lane >> 2, gc2 = (lane & 3) * 2;
    int wm = (warp & 3) * 32;
    int wn = (warp >> 2) * 64;

    const bf16* Ah = g_hh + (size_t)row0 * HID;
    const bf16* Al = g_hl + (size_t)row0 * HID;
    const size_t wb = ((size_t)e * DIM + n0) * HID;
    const bf16* Bh = g_w2h + wb;
    const bf16* Bl = g_w2l + wb;

    float acc[2][8][4];
#pragma unroll
    for (int i = 0; i < 2; i++)
#pragma unroll
        for (int j = 0; j < 8; j++)
#pragma unroll
            for (int q = 0; q < 4; q++) acc[i][j][q] = 0.f;

    uint32_t aAddr = (lane & 15) * SAW + (lane >> 4) * 16;
    uint32_t bAddr = (((lane >> 4) & 1) * 8 + (lane & 7)) * SAW + ((lane >> 3) & 1) * 16;

    const int NK = HID / 32;   // 64
    g2_load(sb, Ah, Al, Bh, Bl, 0, tid);
    cp_commit();

#pragma unroll 1
    for (int kc = 0; kc < NK; kc++) {
        cp_wait0();
        __syncthreads();
        if (kc + 1 < NK) {
            g2_load(sb + ((kc + 1) & 1) * G2_STAGE, Ah, Al, Bh, Bl, (kc + 1) * 32, tid);
            cp_commit();
        }
        uint32_t stv = sb + (kc & 1) * G2_STAGE;
#pragma unroll
        for (int ks = 0; ks < 2; ks++) {
            uint32_t k0b = ks * 32;
            uint32_t ah[2][4], al[2][4];
#pragma unroll
            for (int i = 0; i < 2; i++) {
                uint32_t ra = (wm + i * 16) * SAW + aAddr + k0b;
                ldm_x4(ah[i], stv + G2_AH + ra);
                ldm_x4(al[i], stv + G2_AL + ra);
            }
            uint32_t bh[4][4], bl[4][4];
#pragma unroll
            for (int jp = 0; jp < 4; jp++) {
                uint32_t rb = (wn + jp * 16) * SAW + bAddr + k0b;
                ldm_x4(bh[jp], stv + G2_BH + rb);
                ldm_x4(bl[jp], stv + G2_BL + rb);
            }
#pragma unroll
            for (int i = 0; i < 2; i++)
#pragma unroll
                for (int jp = 0; jp < 4; jp++) {
                    int j0 = jp * 2, j1 = jp * 2 + 1;
                    mma_bf16(acc[i][j0], ah[i], bh[jp][0], bh[jp][1]);
                    mma_bf16(acc[i][j1], ah[i], bh[jp][2], bh[jp][3]);
                    mma_bf16(acc[i][j0], ah[i], bl[jp][0], bl[jp][1]);
                    mma_bf16(acc[i][j1], ah[i], bl[jp][2], bl[jp][3]);
                    mma_bf16(acc[i][j0], al[i], bh[jp][0], bh[jp][1]);
                    mma_bf16(acc[i][j1], al[i], bh[jp][2], bh[jp][3]);
                }
        }
    }

#pragma unroll
    for (int i = 0; i < 2; i++)
#pragma unroll
        for (int j = 0; j < 8; j++) {
            int m = wm + i * 16 + gr;
            int n = wn + j * 8 + gc2;
#pragma unroll
            for (int half = 0; half < 2; half++) {
                int mm = m + half * 8;
                float2 v = make_float2(acc[i][j][half * 2 + 0], acc[i][j][half * 2 + 1]);
                *(float2*)(g_y + (size_t)(row0 + mm) * DIM + n0 + n) = v;
            }
        }
}

// ---------------- launch 5: combine ----------------
__global__ void combine_kernel(float* __restrict__ out) {
    int idx = blockIdx.x * blockDim.x + threadIdx.x;
    if (idx >= T_TOK * DIM / 4) return;
    int t = idx / (DIM / 4);
    int d4 = idx - t * (DIM / 4);
    float w0 = g_gwt[t * 2 + 0], w1 = g_gwt[t * 2 + 1];
    const float4 y0 = *(const float4*)(g_y + (size_t)g_rowOf[t * 2 + 0] * DIM + d4 * 4);
    const float4 y1 = *(const float4*)(g_y + (size_t)g_rowOf[t * 2 + 1] * DIM + d4 * 4);
    float4 o;
    o.x = w0 * y0.x + w1 * y1.x;
    o.y = w0 * y0.y + w1 * y1.y;
    o.z = w0 * y0.z + w1 * y1.z;
    o.w = w0 * y0.w + w1 * y1.w;
    ((float4*)out)[idx] = o;
}

// ---------------- launch ----------------
extern "C" void kernel_launch(void* const* d_in, const int* in_sizes, int n_in,
                              void* d_out, int out_size) {
    const float* x  = (const float*)d_in[0];
    const float* gw = (const float*)d_in[1];
    const float* w1 = (const float*)d_in[2];
    const float* w3 = (const float*)d_in[3];
    const float* w2 = (const float*)d_in[4];
    float* out = (float*)d_out;

    cudaFuncSetAttribute(gemm1_mma, cudaFuncAttributeMaxDynamicSharedMemorySize, G1_SMEM);
    cudaFuncSetAttribute(gemm2_mma, cudaFuncAttributeMaxDynamicSharedMemorySize, G2_SMEM);

    gating_kernel<<<T_TOK / 8, 256>>>(x, gw);                          // 0
    scatscan_kernel<<<1, 1024>>>();                                    // 1
    prep_kernel<<<PADT + WBLK, 256>>>(x, w1, w3, w2);                  // 2
    gemm1_mma<<<dim3(HID / 64, 128, NEXP), 256, G1_SMEM>>>();          // 3 (ncu -s 5 target)
    gemm2_mma<<<dim3(DIM / 128, 128, NEXP), 256, G2_SMEM>>>();         // 4
    combine_kernel<<<(T_TOK * DIM / 4 + 255) / 256, 256>>>(out);       // 5
}